// round 1
// baseline (speedup 1.0000x reference)
#include <cuda_runtime.h>

#define S_LEN 512
#define B_SZ 512
#define T_TAGS 64
#define START_TAG 62
#define STOP_TAG 63

// per-batch result: log_z - gold_score
__device__ float g_res[B_SZ];

__global__ __launch_bounds__(64, 8)
void crf_forward_kernel(const float* __restrict__ feats,
                        const int* __restrict__ tags,
                        const float* __restrict__ mask,
                        const float* __restrict__ trans)
{
    const int b = blockIdx.x;
    const int j = threadIdx.x;            // tag index 0..63
    const int warp = j >> 5, lane = j & 31;

    __shared__ __align__(16) float A[2][T_TAGS];   // double-buffered alpha
    __shared__ float smax[2];
    __shared__ float ssum[2];
    __shared__ float sred[2][2];                   // score partials [warp][{sc,msum}]

    // ---- E column j (exp of transitions) into registers ----
    float Ecol[T_TAGS];
    float w = 1.0f;                                 // 1 + sum_i exp(trans[i][j])  (step-1 analytic weight)
#pragma unroll
    for (int i = 0; i < T_TAGS; i++) {
        Ecol[i] = __expf(__ldg(&trans[i * T_TAGS + j]));  // exp(-10000) flushes to 0
        w += Ecol[i];
    }
    const float Estop = __expf(__ldg(&trans[STOP_TAG * T_TAGS + j]));

    // ---- gold score: parallel over s (prev tag needs no chain) ----
    float sc = 0.0f, msum = 0.0f;
    for (int s = j; s < S_LEN; s += T_TAGS) {
        int   tg = __ldg(&tags[s * B_SZ + b]);
        int   pv = (s == 0) ? START_TAG : __ldg(&tags[(s - 1) * B_SZ + b]);
        float m  = __ldg(&mask[s * B_SZ + b]);
        float e  = __ldg(&feats[(s * B_SZ + b) * T_TAGS + tg]);
        sc   += (e + __ldg(&trans[pv * T_TAGS + tg])) * m;
        msum += m;
    }
#pragma unroll
    for (int off = 16; off; off >>= 1) {
        sc   += __shfl_xor_sync(0xffffffffu, sc, off);
        msum += __shfl_xor_sync(0xffffffffu, msum, off);
    }
    if (lane == 0) { sred[warp][0] = sc; sred[warp][1] = msum; }
    __syncthreads();
    float score_total = 0.0f;
    if (j == 0) {
        float st = sred[0][0] + sred[1][0];
        float mt = sred[0][1] + sred[1][1];
        int   li = (int)(mt + 0.5f) - 1;
        int   lt = __ldg(&tags[li * B_SZ + b]);
        score_total = st + __ldg(&trans[lt * T_TAGS + STOP_TAG]);
    }
    __syncthreads();

    // ---- forward recursion (linear domain, virtual rescaling) ----
    // invariant: true log_alpha[j] = log(A[cur][j]) + C   (plus global -10000 added at end)
    float C = 0.0f;       // accumulated log-scale
    float lmx = 0.0f;     // pending scale of current A (log of its max, or 0)
    float val = 0.0f;     // this thread's current alpha entry (mirror of A[cur][j])
    bool  started = false;
    int   cur = 0;

    float m_cur = __ldg(&mask[b]);
    float f_cur = __ldg(&feats[b * T_TAGS + j]);

    for (int s = 0; s < S_LEN; s++) {
        // prefetch next step's feat/mask to hide LDG latency
        float m_nxt = 0.0f, f_nxt = 0.0f;
        if (s + 1 < S_LEN) {
            m_nxt = __ldg(&mask[(s + 1) * B_SZ + b]);
            f_nxt = __ldg(&feats[((s + 1) * B_SZ + b) * T_TAGS + j]);
        }
        if (m_cur > 0.0f) {                     // uniform across block
            if (started) {
                const float4* a4 = (const float4*)A[cur];
                float acc0 = 0.f, acc1 = 0.f, acc2 = 0.f, acc3 = 0.f;
#pragma unroll
                for (int i4 = 0; i4 < T_TAGS / 4; i4++) {
                    float4 a = a4[i4];           // broadcast LDS.128
                    acc0 = fmaf(a.x, Ecol[4 * i4 + 0], acc0);
                    acc1 = fmaf(a.y, Ecol[4 * i4 + 1], acc1);
                    acc2 = fmaf(a.z, Ecol[4 * i4 + 2], acc2);
                    acc3 = fmaf(a.w, Ecol[4 * i4 + 3], acc3);
                }
                float acc = (acc0 + acc1) + (acc2 + acc3);
                C += lmx;
                val = acc * __expf(f_cur - lmx);
            } else {
                // analytic first step: log_alpha1 = f - 10000 + log(w)
                val = __expf(f_cur) * w;
                started = true;
            }
            int nxt = cur ^ 1;
            A[nxt][j] = val;

            bool rescale = ((s & 3) == 3);
            if (rescale) {
                float v = val;
#pragma unroll
                for (int off = 16; off; off >>= 1)
                    v = fmaxf(v, __shfl_xor_sync(0xffffffffu, v, off));
                if (lane == 0) smax[warp] = v;
            }
            __syncthreads();
            lmx = rescale ? __logf(fmaxf(smax[0], smax[1])) : 0.0f;
            cur = nxt;
        }
        m_cur = m_nxt; f_cur = f_nxt;
    }

    // ---- log_z = C + log( sum_j A[j] * exp(trans[STOP, j]) ) - 10000 ----
    float fv = started ? val : ((j == START_TAG) ? 1.0f : 0.0f);
    if (!started) C = 10000.0f;                 // degenerate all-masked fallback
    float p = fv * Estop;
#pragma unroll
    for (int off = 16; off; off >>= 1)
        p += __shfl_xor_sync(0xffffffffu, p, off);
    if (lane == 0) ssum[warp] = p;
    __syncthreads();
    if (j == 0) {
        float tot  = ssum[0] + ssum[1];
        float logz = C + __logf(tot) - 10000.0f;
        g_res[b] = logz - score_total;
    }
}

__global__ void crf_finalize_kernel(float* __restrict__ out)
{
    const int t = threadIdx.x;                  // 256 threads
    __shared__ float sh[256];
    sh[t] = g_res[t] + g_res[t + 256];
    __syncthreads();
#pragma unroll
    for (int o = 128; o > 0; o >>= 1) {
        if (t < o) sh[t] += sh[t + o];
        __syncthreads();
    }
    if (t == 0) out[0] = sh[0] * (1.0f / (float)B_SZ);
}

extern "C" void kernel_launch(void* const* d_in, const int* in_sizes, int n_in,
                              void* d_out, int out_size)
{
    const float* feats = (const float*)d_in[0];
    const int*   tags  = (const int*)d_in[1];
    const float* mask  = (const float*)d_in[2];
    const float* trans = (const float*)d_in[3];
    float* out = (float*)d_out;

    crf_forward_kernel<<<B_SZ, T_TAGS>>>(feats, tags, mask, trans);
    crf_finalize_kernel<<<1, 256>>>(out);
}